// round 10
// baseline (speedup 1.0000x reference)
#include <cuda_runtime.h>
#include <math.h>
#include <stdint.h>

// ---------------------------------------------------------------------------
// Round 9: round-8 structure with the prep_w1 chunk-indexing bug fixed
// (chunk stride is 2560 float2, not 2048 -> idx>>11 corrupted the layout).
//  prep_w1: W1[320][160] -> g_w1p[chunk][pair][k][2]  (runs once)
//  K2 GEMM1 inner loop: per 2k -> 2 A LDS.128 + 5 B LDS.128 (broadcast, 1 wf)
// ---------------------------------------------------------------------------

#define MTILE 64
#define NTHREADS 256
#define NCHUNK 10
#define CHUNK_FLOATS 2048          // 32 k-rows x 64 nodes
#define MAXBLK 3200
#define W1P_PER_CHUNK 2560         // 80 pairs * 32 k  (float2 elements)

__device__ float g_feat[(size_t)MAXBLK * NCHUNK * CHUNK_FLOATS];
__device__ float2 g_w1p[NCHUNK * W1P_PER_CHUNK];   // [chunk][pair][k] -> {w2p, w2p+1}

typedef unsigned long long ull;

__device__ __forceinline__ ull pk2(float x, float y) {
    ull r; asm("mov.b64 %0, {%1, %2};" : "=l"(r) : "f"(x), "f"(y)); return r;
}
__device__ __forceinline__ void upk2(float& x, float& y, ull v) {
    asm("mov.b64 {%0, %1}, %2;" : "=f"(x), "=f"(y) : "l"(v));
}
__device__ __forceinline__ void fma2(ull& d, ull a, ull b) {
    asm("fma.rn.f32x2 %0, %1, %2, %0;" : "+l"(d) : "l"(a), "l"(b));
}
__device__ __forceinline__ void cpa16(uint32_t dst, const void* src) {
    asm volatile("cp.async.cg.shared.global [%0], [%1], 16;" :: "r"(dst), "l"(src));
}

// ====================== prep: W1 -> pair-k-major layout =====================
__global__ void prep_w1_kernel(const float* __restrict__ W1)
{
    // element (c, p, k): g_w1p[c*2560 + p*32 + k] = {W1[32c+k][2p], W1[32c+k][2p+1]}
    int idx = blockIdx.x * blockDim.x + threadIdx.x;   // 0 .. 25599
    if (idx < NCHUNK * W1P_PER_CHUNK) {
        int c = idx / W1P_PER_CHUNK;          // FIXED: was idx >> 11 (stride 2048)
        int r = idx - c * W1P_PER_CHUNK;
        int p = r >> 5;
        int k = r & 31;
        g_w1p[idx] = *reinterpret_cast<const float2*>(
            &W1[(size_t)(32 * c + k) * 160 + 2 * p]);
    }
}

// ============================ kernel 1: features ============================
#define K1_FEAT   0                 // [32][65] = 2080 floats
#define K1_STAGE  2080              // 64*164 = 10496 -> end 12576
#define K1_SMEM_BYTES (12576 * 4)

__global__ void __launch_bounds__(NTHREADS, 4)
feature_kernel(const float* __restrict__ h,
               const float* __restrict__ v,
               const float* __restrict__ t,
               int N)
{
    extern __shared__ float s[];
    float4* stage4 = reinterpret_cast<float4*>(&s[K1_STAGE]);
    const int tid = threadIdx.x;
    const int m0  = blockIdx.x * MTILE;
    const int mlim = (N - m0 < MTILE) ? (N - m0) : MTILE;
    float* outb = &g_feat[(size_t)blockIdx.x * NCHUNK * CHUNK_FLOATS];
    const float4 z4 = make_float4(0.f, 0.f, 0.f, 0.f);

    for (int c = 0; c < NCHUNK; ++c) {
        if (c < 4) {
            const int kc = c * 32;
            for (int i = tid; i < MTILE * 32; i += NTHREADS) {
                int m = i >> 5, k = i & 31;
                float val = (m < mlim) ? h[(size_t)(m0 + m) * 128 + kc + k] : 0.f;
                s[K1_FEAT + k * 65 + m] = val;
            }
        } else if (c < 6) {
            const int j0 = (c - 4) * 32;
            for (int i = tid; i < MTILE * 24; i += NTHREADS) {
                int nd = i / 24, q = i - nd * 24;
                stage4[nd * 24 + q] = (nd < mlim)
                    ? reinterpret_cast<const float4*>(v)[
                          (size_t)(m0 + nd) * 48 + (j0 >> 2) * 3 + q]
                    : z4;
            }
            __syncthreads();
            for (int i = tid; i < MTILE * 32; i += NTHREADS) {
                int m = i >> 5, k = i & 31;
                const float* sp = &s[K1_STAGE + m * 96 + k * 3];
                s[K1_FEAT + k * 65 + m] =
                    sqrtf(sp[0]*sp[0] + sp[1]*sp[1] + sp[2]*sp[2]);
            }
        } else {
            const int c0 = (c - 6) * 16;
            for (int i = tid; i < MTILE * 36; i += NTHREADS) {
                int nd = i / 36, q = i - nd * 36;
                stage4[nd * 41 + q] = (nd < mlim)
                    ? reinterpret_cast<const float4*>(t)[
                          (size_t)(m0 + nd) * 144 + (c0 >> 2) * 9 + q]
                    : z4;
            }
            __syncthreads();
            for (int i = tid; i < MTILE * 16; i += NTHREADS) {
                int m = i >> 4, cc = i & 15;
                const float* sp = &s[K1_STAGE + m * 164 + cc * 9];
                float q0 = sp[0], q1 = sp[1], q2 = sp[2];
                float q3 = sp[3], q4 = sp[4], q5 = sp[5];
                float q6 = sp[6], q7 = sp[7], q8 = sp[8];
                float tr = q0 + q4 + q8;
                float fb = sqrtf(q0*q0 + q1*q1 + q2*q2 + q3*q3 + q4*q4 +
                                 q5*q5 + q6*q6 + q7*q7 + q8*q8);
                s[K1_FEAT + (2 * cc)     * 65 + m] = tr;
                s[K1_FEAT + (2 * cc + 1) * 65 + m] = fb;
            }
        }
        __syncthreads();
        for (int i = tid; i < CHUNK_FLOATS; i += NTHREADS) {
            int k = i >> 6, m = i & 63;
            outb[c * CHUNK_FLOATS + i] = s[K1_FEAT + k * 65 + m];
        }
        __syncthreads();
    }
}

// ========================= kernel 2: GEMM + epilogue ========================
#define OFF_FA     0            // feat bufs [2][2048] = 4096
#define OFF_W1B    4096         // w1p bufs [2][5120] = 10240 (end 14336)
#define OFF_HT     0            // hT [160][68] = 10880 (phase 2)
#define OFF_ALPHA  0            // alpha [64][65] = 4160 (phase 3+)
#define OFF_GS     4160         // Gs [64][9] = 576
#define OFF_BATCH  4736         // batch[64] ints
#define OFF_EST    4800         // epilogue t stage 64*164 = 10496 (end 15296)
#define K2_SMEM_FLOATS 15296
#define K2_SMEM_BYTES  (K2_SMEM_FLOATS * 4)

__global__ void __launch_bounds__(NTHREADS, 3)
gemm_pool_kernel(const float* __restrict__ t,
                 const float* __restrict__ frames,
                 const int* __restrict__ batch,
                 const float* __restrict__ b1,
                 const float* __restrict__ W2,
                 const float* __restrict__ b2,
                 float* __restrict__ out,
                 int N, int num_graphs)
{
    extern __shared__ float s[];
    const int tid = threadIdx.x;
    const int m0  = blockIdx.x * MTILE;
    const int mlim = (N - m0 < MTILE) ? (N - m0) : MTILE;
    const uint32_t sbase = (uint32_t)__cvta_generic_to_shared(s);
    const float* featb = &g_feat[(size_t)blockIdx.x * NCHUNK * CHUNK_FLOATS];
    const float* w1pf  = reinterpret_cast<const float*>(g_w1p);

    // ---------------- GEMM1: async double-buffered over 10 chunks -----------
    const int tm = (tid & 15) * 4;     // 4 node-rows
    const int tn = (tid >> 4) * 10;    // 10 hidden cols
    const int p0 = (tid >> 4) * 5;     // 5 column-pairs in w1p layout

    ull accp[4][5];
#pragma unroll
    for (int i = 0; i < 4; ++i)
#pragma unroll
        for (int j = 0; j < 5; ++j) accp[i][j] = 0ULL;

#define ISSUE_CHUNK(c)                                                        \
    do {                                                                      \
        const int _b = (c) & 1;                                               \
        const float* fsrc = featb + (c) * CHUNK_FLOATS;                       \
        uint32_t fdst = sbase + (OFF_FA + _b * 2048) * 4;                     \
        for (int i = tid; i < 512; i += NTHREADS)                             \
            cpa16(fdst + i * 16, fsrc + i * 4);                               \
        const float* wsrc = w1pf + (size_t)(c) * 5120;                        \
        uint32_t wdst = sbase + (OFF_W1B + _b * 5120) * 4;                    \
        for (int i = tid; i < 1280; i += NTHREADS)                            \
            cpa16(wdst + i * 16, wsrc + i * 4);                               \
        asm volatile("cp.async.commit_group;");                               \
    } while (0)

    ISSUE_CHUNK(0);
    for (int c = 0; c < NCHUNK; ++c) {
        asm volatile("cp.async.wait_group 0;");
        __syncthreads();
        if (c + 1 < NCHUNK) ISSUE_CHUNK(c + 1);

        const float* fb = &s[OFF_FA  + (c & 1) * 2048];
        const float* wb = &s[OFF_W1B + (c & 1) * 5120];  // [80 pairs][32 k][2]
#pragma unroll 4
        for (int k = 0; k < 32; k += 2) {
            const float4 a4 = *reinterpret_cast<const float4*>(&fb[k * 64 + tm]);
            const float4 a5 = *reinterpret_cast<const float4*>(&fb[(k + 1) * 64 + tm]);
            ull av0[4], av1[4];
            av0[0] = pk2(a4.x, a4.x);  av0[1] = pk2(a4.y, a4.y);
            av0[2] = pk2(a4.z, a4.z);  av0[3] = pk2(a4.w, a4.w);
            av1[0] = pk2(a5.x, a5.x);  av1[1] = pk2(a5.y, a5.y);
            av1[2] = pk2(a5.z, a5.z);  av1[3] = pk2(a5.w, a5.w);
#pragma unroll
            for (int j = 0; j < 5; ++j) {
                // one LDS.128: pair (p0+j) at k and k+1
                const ulonglong2 b = *reinterpret_cast<const ulonglong2*>(
                    &wb[(p0 + j) * 64 + 2 * k]);
#pragma unroll
                for (int i = 0; i < 4; ++i) {
                    fma2(accp[i][j], av0[i], b.x);
                    fma2(accp[i][j], av1[i], b.y);
                }
            }
        }
    }
    __syncthreads();   // buffers dead; hT overlays

    // ---------------- bias + SiLU -> hT [160][68] ---------------------------
#pragma unroll
    for (int j2 = 0; j2 < 5; ++j2) {
        const float b_lo = b1[tn + 2 * j2];
        const float b_hi = b1[tn + 2 * j2 + 1];
#pragma unroll
        for (int i = 0; i < 4; ++i) {
            float lo, hi;
            upk2(lo, hi, accp[i][j2]);
            float x0 = lo + b_lo, x1 = hi + b_hi;
            s[OFF_HT + (tn + 2 * j2)     * 68 + tm + i] = x0 / (1.0f + __expf(-x0));
            s[OFF_HT + (tn + 2 * j2 + 1) * 68 + tm + i] = x1 / (1.0f + __expf(-x1));
        }
    }
    __syncthreads();

    // ---------------- GEMM2: [64,160] @ [160,64] ----------------------------
    const int tn2 = (tid >> 4) * 4;
    ull acc2p[4][2];
#pragma unroll
    for (int i = 0; i < 4; ++i) { acc2p[i][0] = 0ULL; acc2p[i][1] = 0ULL; }

#pragma unroll 4
    for (int k = 0; k < 160; ++k) {
        const float4 a4 = *reinterpret_cast<const float4*>(&s[OFF_HT + k * 68 + tm]);
        const ulonglong2 b2v = *reinterpret_cast<const ulonglong2*>(
            &W2[(size_t)k * 64 + tn2]);
        ull avd[4];
        avd[0] = pk2(a4.x, a4.x);
        avd[1] = pk2(a4.y, a4.y);
        avd[2] = pk2(a4.z, a4.z);
        avd[3] = pk2(a4.w, a4.w);
#pragma unroll
        for (int i = 0; i < 4; ++i) {
            fma2(acc2p[i][0], avd[i], b2v.x);
            fma2(acc2p[i][1], avd[i], b2v.y);
        }
    }
    __syncthreads();   // hT dead; alpha overlays

    {
        const float b_0 = b2[tn2 + 0], b_1 = b2[tn2 + 1];
        const float b_2 = b2[tn2 + 2], b_3 = b2[tn2 + 3];
#pragma unroll
        for (int i = 0; i < 4; ++i) {
            float a0, a1, a2, a3;
            upk2(a0, a1, acc2p[i][0]);
            upk2(a2, a3, acc2p[i][1]);
            float* ap = &s[OFF_ALPHA + (tm + i) * 65 + tn2];
            ap[0] = a0 + b_0;
            ap[1] = a1 + b_1;
            ap[2] = a2 + b_2;
            ap[3] = a3 + b_3;
        }
    }
    if (tid < MTILE)
        reinterpret_cast<int*>(s)[OFF_BATCH + tid] =
            (tid < mlim) ? batch[m0 + tid] : -1;
    __syncthreads();

    // ---------------- epilogue: staged gated sum over 4 t-chunks ------------
    float4* stage4 = reinterpret_cast<float4*>(&s[OFF_EST]);
    const int node = tid >> 2;
    const int jj   = tid & 3;
    float g[9];
#pragma unroll
    for (int k = 0; k < 9; ++k) g[k] = 0.0f;

    const float4 z4 = make_float4(0.f, 0.f, 0.f, 0.f);
    for (int chunk = 0; chunk < 4; ++chunk) {
        for (int i = tid; i < MTILE * 36; i += NTHREADS) {
            int nd = i / 36, q = i - nd * 36;
            stage4[nd * 41 + q] = (nd < mlim)
                ? reinterpret_cast<const float4*>(t)[
                      (size_t)(m0 + nd) * 144 + chunk * 36 + q]
                : z4;
        }
        __syncthreads();
        if (node < mlim) {
            const float* ap = &s[OFF_ALPHA + node * 65 + chunk * 16];
#pragma unroll
            for (int cc = 0; cc < 4; ++cc) {
                const int ch = jj + 4 * cc;
                const float al = ap[ch];
                const float* f = &s[OFF_EST + node * 164 + ch * 9];
#pragma unroll
                for (int k = 0; k < 9; ++k)
                    g[k] = fmaf(al, f[k], g[k]);
            }
        }
        __syncthreads();
    }

#pragma unroll
    for (int k = 0; k < 9; ++k) {
        g[k] += __shfl_xor_sync(0xFFFFFFFFu, g[k], 1);
        g[k] += __shfl_xor_sync(0xFFFFFFFFu, g[k], 2);
    }

    if (jj == 0) {
        float G[9];
        if (node < mlim) {
            float S[9];
#pragma unroll
            for (int a = 0; a < 3; ++a)
#pragma unroll
                for (int b = 0; b < 3; ++b)
                    S[a * 3 + b] = 0.5f * (g[a * 3 + b] + g[b * 3 + a]);
            const float* rp = frames + (size_t)(m0 + node) * 9;
            float R[9];
#pragma unroll
            for (int k = 0; k < 9; ++k) R[k] = rp[k];
            float P[9];
#pragma unroll
            for (int a = 0; a < 3; ++a)
#pragma unroll
                for (int c = 0; c < 3; ++c)
                    P[a * 3 + c] = R[a * 3 + 0] * S[0 * 3 + c]
                                 + R[a * 3 + 1] * S[1 * 3 + c]
                                 + R[a * 3 + 2] * S[2 * 3 + c];
#pragma unroll
            for (int a = 0; a < 3; ++a)
#pragma unroll
                for (int d = 0; d < 3; ++d)
                    G[a * 3 + d] = P[a * 3 + 0] * R[d * 3 + 0]
                                 + P[a * 3 + 1] * R[d * 3 + 1]
                                 + P[a * 3 + 2] * R[d * 3 + 2];
        } else {
#pragma unroll
            for (int k = 0; k < 9; ++k) G[k] = 0.0f;
        }
#pragma unroll
        for (int k = 0; k < 9; ++k) s[OFF_GS + node * 9 + k] = G[k];
    }
    __syncthreads();

    // ---------------- sorted-run segment sum --------------------------------
    if (tid < 9) {
        const int* bs = reinterpret_cast<const int*>(s) + OFF_BATCH;
        int cur = bs[0];
        float run = 0.0f;
        for (int n = 0; n < mlim; ++n) {
            int b = bs[n];
            if (b != cur) {
                if ((unsigned)cur < (unsigned)num_graphs)
                    atomicAdd(&out[(size_t)cur * 9 + tid], run);
                run = 0.0f;
                cur = b;
            }
            run += s[OFF_GS + n * 9 + tid];
        }
        if ((unsigned)cur < (unsigned)num_graphs)
            atomicAdd(&out[(size_t)cur * 9 + tid], run);
    }
}

// ================================ launcher ==================================
extern "C" void kernel_launch(void* const* d_in, const int* in_sizes, int n_in,
                              void* d_out, int out_size)
{
    const float* h      = (const float*)d_in[0];
    const float* v      = (const float*)d_in[1];
    const float* t      = (const float*)d_in[2];
    const float* frames = (const float*)d_in[3];
    const int*   batch  = (const int*)d_in[4];
    const float* W1     = (const float*)d_in[5];
    const float* b1     = (const float*)d_in[6];
    const float* W2     = (const float*)d_in[7];
    const float* b2     = (const float*)d_in[8];
    float* out = (float*)d_out;

    const int N = in_sizes[0] / 128;
    const int num_graphs = out_size / 9;
    const int grid = (N + MTILE - 1) / MTILE;

    cudaMemsetAsync(d_out, 0, (size_t)out_size * sizeof(float));

    cudaFuncSetAttribute(feature_kernel,
                         cudaFuncAttributeMaxDynamicSharedMemorySize, K1_SMEM_BYTES);
    cudaFuncSetAttribute(gemm_pool_kernel,
                         cudaFuncAttributeMaxDynamicSharedMemorySize, K2_SMEM_BYTES);

    prep_w1_kernel<<<100, 256>>>(W1);
    feature_kernel<<<grid, NTHREADS, K1_SMEM_BYTES>>>(h, v, t, N);
    gemm_pool_kernel<<<grid, NTHREADS, K2_SMEM_BYTES>>>(
        t, frames, batch, b1, W2, b2, out, N, num_graphs);
}

// round 11
// speedup vs baseline: 1.1931x; 1.1931x over previous
#include <cuda_runtime.h>
#include <math.h>
#include <stdint.h>

// ---------------------------------------------------------------------------
// Round 10: fully fused, cp.async-pipelined RAW-input streaming.
// 20 K-chunks of 16 feature rows; per chunk the raw slab (h / v / t) and the
// W1 slice are double-buffered via cp.async; the in-smem transform + FFMA2
// run under the next chunk's DMA. No g_feat round-trip, no serial prefix.
// ---------------------------------------------------------------------------

#define MTILE 64
#define NTHREADS 256
#define NCHUNK 20                 // 20 x 16 = 320 feature rows

// smem float offsets (GEMM phase)
#define OFF_W1B   0               // W1 bufs [2][16*160]  = 5120
#define OFF_RAW   5120            // raw bufs [2][4608]   = 9216 (end 14336)
#define OFF_FEAT  14336           // feat [16][68]        = 1088 (end 15424)
// overlays (after GEMM1 barrier)
#define OFF_HT    0               // hT [160][68] = 10880
#define OFF_ALPHA 0               // alpha [64][65] = 4160
#define OFF_GS    4160            // Gs [64][9] = 576
#define OFF_BATCH 4736            // batch[64] ints
#define OFF_EST   4800            // epilogue t stage 64*164 = 10496 (end 15296)
#define SMEM_FLOATS 15424
#define SMEM_BYTES  (SMEM_FLOATS * 4)

typedef unsigned long long ull;

__device__ __forceinline__ ull pk2(float x, float y) {
    ull r; asm("mov.b64 %0, {%1, %2};" : "=l"(r) : "f"(x), "f"(y)); return r;
}
__device__ __forceinline__ void upk2(float& x, float& y, ull v) {
    asm("mov.b64 {%0, %1}, %2;" : "=f"(x), "=f"(y) : "l"(v));
}
__device__ __forceinline__ void fma2(ull& d, ull a, ull b) {
    asm("fma.rn.f32x2 %0, %1, %2, %0;" : "+l"(d) : "l"(a), "l"(b));
}
__device__ __forceinline__ void cpa16(uint32_t dst, const void* src) {
    asm volatile("cp.async.cg.shared.global [%0], [%1], 16;" :: "r"(dst), "l"(src));
}

__global__ void __launch_bounds__(NTHREADS, 3)
tensor_message_fused(const float* __restrict__ h,
                     const float* __restrict__ v,
                     const float* __restrict__ t,
                     const float* __restrict__ frames,
                     const int* __restrict__ batch,
                     const float* __restrict__ W1,
                     const float* __restrict__ b1,
                     const float* __restrict__ W2,
                     const float* __restrict__ b2,
                     float* __restrict__ out,
                     int N, int num_graphs)
{
    extern __shared__ float s[];
    const int tid  = threadIdx.x;
    const int m0   = blockIdx.x * MTILE;
    const int mlim = (N - m0 < MTILE) ? (N - m0) : MTILE;
    const uint32_t sbase = (uint32_t)__cvta_generic_to_shared(s);

    const int tm = (tid & 15) * 4;     // 4 node-rows
    const int tn = (tid >> 4) * 10;    // 10 hidden cols (5 packed pairs)

    ull accp[4][5];
#pragma unroll
    for (int i = 0; i < 4; ++i)
#pragma unroll
        for (int j = 0; j < 5; ++j) accp[i][j] = 0ULL;

    // ---- async issue of chunk c's raw slab + W1 slice ----------------------
    // raw layouts per buffer (floats): h [64][16], v [64][48], t [64][72]
#define ISSUE_CHUNK(c)                                                        \
    do {                                                                      \
        const int _b = (c) & 1;                                               \
        const uint32_t rdst = sbase + (OFF_RAW + _b * 4608) * 4;              \
        if ((c) < 8) {                                                        \
            for (int i = tid; i < 256; i += NTHREADS) {                       \
                int m = i >> 2, q = i & 3;                                    \
                if (m < mlim)                                                 \
                    cpa16(rdst + (m * 16 + q * 4) * 4,                        \
                          h + (size_t)(m0 + m) * 128 + (c) * 16 + q * 4);     \
            }                                                                 \
        } else if ((c) < 12) {                                                \
            for (int i = tid; i < 768; i += NTHREADS) {                       \
                int m = i / 12, q = i - m * 12;                               \
                if (m < mlim)                                                 \
                    cpa16(rdst + (m * 48 + q * 4) * 4,                        \
                          v + (size_t)(m0 + m) * 192 + ((c) - 8) * 48 + q * 4); \
            }                                                                 \
        } else {                                                              \
            for (int i = tid; i < 1152; i += NTHREADS) {                      \
                int m = i / 18, q = i - m * 18;                               \
                if (m < mlim)                                                 \
                    cpa16(rdst + (m * 72 + q * 4) * 4,                        \
                          t + (size_t)(m0 + m) * 576 + ((c) - 12) * 72 + q * 4); \
            }                                                                 \
        }                                                                     \
        const uint32_t wdst = sbase + (OFF_W1B + _b * 2560) * 4;              \
        const float* wsrc = W1 + (size_t)(c) * 2560;                          \
        for (int i = tid; i < 640; i += NTHREADS)                             \
            cpa16(wdst + i * 16, wsrc + i * 4);                               \
        asm volatile("cp.async.commit_group;");                               \
    } while (0)

    ISSUE_CHUNK(0);
    for (int c = 0; c < NCHUNK; ++c) {
        asm volatile("cp.async.wait_group 0;");
        __syncthreads();               // raw(c)/W1(c) visible; feat(c-1) consumed
        if (c + 1 < NCHUNK) ISSUE_CHUNK(c + 1);

        const float* raw = &s[OFF_RAW + (c & 1) * 4608];
        // ---- transform raw(c) -> feat [16][68] ----
        if (c < 8) {
            for (int i = tid; i < MTILE * 16; i += NTHREADS) {
                int m = i >> 4, k = i & 15;
                s[OFF_FEAT + k * 68 + m] = raw[m * 16 + k];
            }
        } else if (c < 12) {
            for (int i = tid; i < MTILE * 16; i += NTHREADS) {
                int m = i >> 4, k = i & 15;
                const float* sp = &raw[m * 48 + k * 3];
                s[OFF_FEAT + k * 68 + m] =
                    sqrtf(sp[0]*sp[0] + sp[1]*sp[1] + sp[2]*sp[2]);
            }
        } else {
            for (int i = tid; i < MTILE * 8; i += NTHREADS) {
                int m = i >> 3, cc = i & 7;
                const float* sp = &raw[m * 72 + cc * 9];
                float q0 = sp[0], q1 = sp[1], q2 = sp[2];
                float q3 = sp[3], q4 = sp[4], q5 = sp[5];
                float q6 = sp[6], q7 = sp[7], q8 = sp[8];
                float tr = q0 + q4 + q8;
                float fb = sqrtf(q0*q0 + q1*q1 + q2*q2 + q3*q3 + q4*q4 +
                                 q5*q5 + q6*q6 + q7*q7 + q8*q8);
                s[OFF_FEAT + (2 * cc)     * 68 + m] = tr;
                s[OFF_FEAT + (2 * cc + 1) * 68 + m] = fb;
            }
        }
        __syncthreads();               // feat(c) ready

        // ---- GEMM1 FMA over 16 k-rows (round-7 inner loop) ----
        const float* wb = &s[OFF_W1B + (c & 1) * 2560];
#pragma unroll 4
        for (int k = 0; k < 16; ++k) {
            const float4 a4 = *reinterpret_cast<const float4*>(
                &s[OFF_FEAT + k * 68 + tm]);
            ull avd[4];
            avd[0] = pk2(a4.x, a4.x);
            avd[1] = pk2(a4.y, a4.y);
            avd[2] = pk2(a4.z, a4.z);
            avd[3] = pk2(a4.w, a4.w);
            const ull* bp = reinterpret_cast<const ull*>(&wb[k * 160 + tn]);
            ull bv2[5];
#pragma unroll
            for (int j = 0; j < 5; ++j) bv2[j] = bp[j];
#pragma unroll
            for (int i = 0; i < 4; ++i)
#pragma unroll
                for (int j = 0; j < 5; ++j)
                    fma2(accp[i][j], avd[i], bv2[j]);
        }
    }
    __syncthreads();   // buffers dead; hT overlays

    // ---------------- bias + SiLU -> hT [160][68] ---------------------------
#pragma unroll
    for (int j2 = 0; j2 < 5; ++j2) {
        const float b_lo = b1[tn + 2 * j2];
        const float b_hi = b1[tn + 2 * j2 + 1];
#pragma unroll
        for (int i = 0; i < 4; ++i) {
            float lo, hi;
            upk2(lo, hi, accp[i][j2]);
            float x0 = lo + b_lo, x1 = hi + b_hi;
            s[OFF_HT + (tn + 2 * j2)     * 68 + tm + i] = x0 / (1.0f + __expf(-x0));
            s[OFF_HT + (tn + 2 * j2 + 1) * 68 + tm + i] = x1 / (1.0f + __expf(-x1));
        }
    }
    __syncthreads();

    // ---------------- GEMM2: [64,160] @ [160,64] ----------------------------
    const int tn2 = (tid >> 4) * 4;
    ull acc2p[4][2];
#pragma unroll
    for (int i = 0; i < 4; ++i) { acc2p[i][0] = 0ULL; acc2p[i][1] = 0ULL; }

#pragma unroll 4
    for (int k = 0; k < 160; ++k) {
        const float4 a4 = *reinterpret_cast<const float4*>(&s[OFF_HT + k * 68 + tm]);
        const ulonglong2 b2v = *reinterpret_cast<const ulonglong2*>(
            &W2[(size_t)k * 64 + tn2]);
        ull avd[4];
        avd[0] = pk2(a4.x, a4.x);
        avd[1] = pk2(a4.y, a4.y);
        avd[2] = pk2(a4.z, a4.z);
        avd[3] = pk2(a4.w, a4.w);
#pragma unroll
        for (int i = 0; i < 4; ++i) {
            fma2(acc2p[i][0], avd[i], b2v.x);
            fma2(acc2p[i][1], avd[i], b2v.y);
        }
    }
    __syncthreads();   // hT dead; alpha overlays

    {
        const float b_0 = b2[tn2 + 0], b_1 = b2[tn2 + 1];
        const float b_2 = b2[tn2 + 2], b_3 = b2[tn2 + 3];
#pragma unroll
        for (int i = 0; i < 4; ++i) {
            float a0, a1, a2, a3;
            upk2(a0, a1, acc2p[i][0]);
            upk2(a2, a3, acc2p[i][1]);
            float* ap = &s[OFF_ALPHA + (tm + i) * 65 + tn2];
            ap[0] = a0 + b_0;
            ap[1] = a1 + b_1;
            ap[2] = a2 + b_2;
            ap[3] = a3 + b_3;
        }
    }
    if (tid < MTILE)
        reinterpret_cast<int*>(s)[OFF_BATCH + tid] =
            (tid < mlim) ? batch[m0 + tid] : -1;
    __syncthreads();

    // ---------------- epilogue: staged gated sum over 4 t-chunks ------------
    float4* stage4 = reinterpret_cast<float4*>(&s[OFF_EST]);
    const int node = tid >> 2;
    const int jj   = tid & 3;
    float g[9];
#pragma unroll
    for (int k = 0; k < 9; ++k) g[k] = 0.0f;

    const float4 z4 = make_float4(0.f, 0.f, 0.f, 0.f);
    for (int chunk = 0; chunk < 4; ++chunk) {
        for (int i = tid; i < MTILE * 36; i += NTHREADS) {
            int nd = i / 36, q = i - nd * 36;
            stage4[nd * 41 + q] = (nd < mlim)
                ? reinterpret_cast<const float4*>(t)[
                      (size_t)(m0 + nd) * 144 + chunk * 36 + q]
                : z4;
        }
        __syncthreads();
        if (node < mlim) {
            const float* ap = &s[OFF_ALPHA + node * 65 + chunk * 16];
#pragma unroll
            for (int cc = 0; cc < 4; ++cc) {
                const int ch = jj + 4 * cc;
                const float al = ap[ch];
                const float* f = &s[OFF_EST + node * 164 + ch * 9];
#pragma unroll
                for (int k = 0; k < 9; ++k)
                    g[k] = fmaf(al, f[k], g[k]);
            }
        }
        __syncthreads();
    }

#pragma unroll
    for (int k = 0; k < 9; ++k) {
        g[k] += __shfl_xor_sync(0xFFFFFFFFu, g[k], 1);
        g[k] += __shfl_xor_sync(0xFFFFFFFFu, g[k], 2);
    }

    if (jj == 0) {
        float G[9];
        if (node < mlim) {
            float S[9];
#pragma unroll
            for (int a = 0; a < 3; ++a)
#pragma unroll
                for (int b = 0; b < 3; ++b)
                    S[a * 3 + b] = 0.5f * (g[a * 3 + b] + g[b * 3 + a]);
            const float* rp = frames + (size_t)(m0 + node) * 9;
            float R[9];
#pragma unroll
            for (int k = 0; k < 9; ++k) R[k] = rp[k];
            float P[9];
#pragma unroll
            for (int a = 0; a < 3; ++a)
#pragma unroll
                for (int c = 0; c < 3; ++c)
                    P[a * 3 + c] = R[a * 3 + 0] * S[0 * 3 + c]
                                 + R[a * 3 + 1] * S[1 * 3 + c]
                                 + R[a * 3 + 2] * S[2 * 3 + c];
#pragma unroll
            for (int a = 0; a < 3; ++a)
#pragma unroll
                for (int d = 0; d < 3; ++d)
                    G[a * 3 + d] = P[a * 3 + 0] * R[d * 3 + 0]
                                 + P[a * 3 + 1] * R[d * 3 + 1]
                                 + P[a * 3 + 2] * R[d * 3 + 2];
        } else {
#pragma unroll
            for (int k = 0; k < 9; ++k) G[k] = 0.0f;
        }
#pragma unroll
        for (int k = 0; k < 9; ++k) s[OFF_GS + node * 9 + k] = G[k];
    }
    __syncthreads();

    // ---------------- sorted-run segment sum --------------------------------
    if (tid < 9) {
        const int* bs = reinterpret_cast<const int*>(s) + OFF_BATCH;
        int cur = bs[0];
        float run = 0.0f;
        for (int n = 0; n < mlim; ++n) {
            int b = bs[n];
            if (b != cur) {
                if ((unsigned)cur < (unsigned)num_graphs)
                    atomicAdd(&out[(size_t)cur * 9 + tid], run);
                run = 0.0f;
                cur = b;
            }
            run += s[OFF_GS + n * 9 + tid];
        }
        if ((unsigned)cur < (unsigned)num_graphs)
            atomicAdd(&out[(size_t)cur * 9 + tid], run);
    }
}

// ================================ launcher ==================================
extern "C" void kernel_launch(void* const* d_in, const int* in_sizes, int n_in,
                              void* d_out, int out_size)
{
    const float* h      = (const float*)d_in[0];
    const float* v      = (const float*)d_in[1];
    const float* t      = (const float*)d_in[2];
    const float* frames = (const float*)d_in[3];
    const int*   batch  = (const int*)d_in[4];
    const float* W1     = (const float*)d_in[5];
    const float* b1     = (const float*)d_in[6];
    const float* W2     = (const float*)d_in[7];
    const float* b2     = (const float*)d_in[8];
    float* out = (float*)d_out;

    const int N = in_sizes[0] / 128;
    const int num_graphs = out_size / 9;
    const int grid = (N + MTILE - 1) / MTILE;

    cudaMemsetAsync(d_out, 0, (size_t)out_size * sizeof(float));

    cudaFuncSetAttribute(tensor_message_fused,
                         cudaFuncAttributeMaxDynamicSharedMemorySize, SMEM_BYTES);

    tensor_message_fused<<<grid, NTHREADS, SMEM_BYTES>>>(
        h, v, t, frames, batch, W1, b1, W2, b2, out, N, num_graphs);
}

// round 16
// speedup vs baseline: 1.2935x; 1.0842x over previous
#include <cuda_runtime.h>
#include <math.h>
#include <stdint.h>

// ---------------------------------------------------------------------------
// Round 11: round-10 fused pipeline + cp.async double-buffered EPILOGUE.
// The t re-read (gated sum) was the last exposed-latency phase: now 8 chunks
// of 8 channels, prefetched 2 deep, stage pitch 76 (bank-conflict-free for
// the (node, jj) gated-sum read pattern). GEMM path identical to round 10.
// ---------------------------------------------------------------------------

#define MTILE 64
#define NTHREADS 256
#define NCHUNK 20                 // 20 x 16 = 320 feature rows

// smem float offsets (GEMM phase)
#define OFF_W1B   0               // W1 bufs [2][16*160]  = 5120
#define OFF_RAW   5120            // raw bufs [2][4608]   = 9216 (end 14336)
#define OFF_FEAT  14336           // feat [16][68]        = 1088 (end 15424)
// overlays (after GEMM1 barrier)
#define OFF_HT    0               // hT [160][68] = 10880
#define OFF_ALPHA 0               // alpha [64][65] = 4160
#define OFF_GS    4160            // Gs [64][9] = 576
#define OFF_BATCH 4736            // batch[64] ints
#define OFF_EST   4800            // epilogue t bufs [2][64*76] = 9728 (end 14528)
#define EPITCH    76              // 72 + 4 pad: 12n+9jj mod 32 all-distinct
#define SMEM_FLOATS 15424
#define SMEM_BYTES  (SMEM_FLOATS * 4)

typedef unsigned long long ull;

__device__ __forceinline__ ull pk2(float x, float y) {
    ull r; asm("mov.b64 %0, {%1, %2};" : "=l"(r) : "f"(x), "f"(y)); return r;
}
__device__ __forceinline__ void upk2(float& x, float& y, ull v) {
    asm("mov.b64 {%0, %1}, %2;" : "=f"(x), "=f"(y) : "l"(v));
}
__device__ __forceinline__ void fma2(ull& d, ull a, ull b) {
    asm("fma.rn.f32x2 %0, %1, %2, %0;" : "+l"(d) : "l"(a), "l"(b));
}
__device__ __forceinline__ void cpa16(uint32_t dst, const void* src) {
    asm volatile("cp.async.cg.shared.global [%0], [%1], 16;" :: "r"(dst), "l"(src));
}

__global__ void __launch_bounds__(NTHREADS, 3)
tensor_message_fused(const float* __restrict__ h,
                     const float* __restrict__ v,
                     const float* __restrict__ t,
                     const float* __restrict__ frames,
                     const int* __restrict__ batch,
                     const float* __restrict__ W1,
                     const float* __restrict__ b1,
                     const float* __restrict__ W2,
                     const float* __restrict__ b2,
                     float* __restrict__ out,
                     int N, int num_graphs)
{
    extern __shared__ float s[];
    const int tid  = threadIdx.x;
    const int m0   = blockIdx.x * MTILE;
    const int mlim = (N - m0 < MTILE) ? (N - m0) : MTILE;
    const uint32_t sbase = (uint32_t)__cvta_generic_to_shared(s);

    const int tm = (tid & 15) * 4;     // 4 node-rows
    const int tn = (tid >> 4) * 10;    // 10 hidden cols (5 packed pairs)

    ull accp[4][5];
#pragma unroll
    for (int i = 0; i < 4; ++i)
#pragma unroll
        for (int j = 0; j < 5; ++j) accp[i][j] = 0ULL;

    // ---- async issue of chunk c's raw slab + W1 slice ----------------------
#define ISSUE_CHUNK(c)                                                        \
    do {                                                                      \
        const int _b = (c) & 1;                                               \
        const uint32_t rdst = sbase + (OFF_RAW + _b * 4608) * 4;              \
        if ((c) < 8) {                                                        \
            for (int i = tid; i < 256; i += NTHREADS) {                       \
                int m = i >> 2, q = i & 3;                                    \
                if (m < mlim)                                                 \
                    cpa16(rdst + (m * 16 + q * 4) * 4,                        \
                          h + (size_t)(m0 + m) * 128 + (c) * 16 + q * 4);     \
            }                                                                 \
        } else if ((c) < 12) {                                                \
            for (int i = tid; i < 768; i += NTHREADS) {                       \
                int m = i / 12, q = i - m * 12;                               \
                if (m < mlim)                                                 \
                    cpa16(rdst + (m * 48 + q * 4) * 4,                        \
                          v + (size_t)(m0 + m) * 192 + ((c) - 8) * 48 + q * 4); \
            }                                                                 \
        } else {                                                              \
            for (int i = tid; i < 1152; i += NTHREADS) {                      \
                int m = i / 18, q = i - m * 18;                               \
                if (m < mlim)                                                 \
                    cpa16(rdst + (m * 72 + q * 4) * 4,                        \
                          t + (size_t)(m0 + m) * 576 + ((c) - 12) * 72 + q * 4); \
            }                                                                 \
        }                                                                     \
        const uint32_t wdst = sbase + (OFF_W1B + _b * 2560) * 4;              \
        const float* wsrc = W1 + (size_t)(c) * 2560;                          \
        for (int i = tid; i < 640; i += NTHREADS)                             \
            cpa16(wdst + i * 16, wsrc + i * 4);                               \
        asm volatile("cp.async.commit_group;");                               \
    } while (0)

    ISSUE_CHUNK(0);
    for (int c = 0; c < NCHUNK; ++c) {
        asm volatile("cp.async.wait_group 0;");
        __syncthreads();               // raw(c)/W1(c) visible; feat(c-1) consumed
        if (c + 1 < NCHUNK) ISSUE_CHUNK(c + 1);

        const float* raw = &s[OFF_RAW + (c & 1) * 4608];
        // ---- transform raw(c) -> feat [16][68] ----
        if (c < 8) {
            for (int i = tid; i < MTILE * 16; i += NTHREADS) {
                int m = i >> 4, k = i & 15;
                s[OFF_FEAT + k * 68 + m] = raw[m * 16 + k];
            }
        } else if (c < 12) {
            for (int i = tid; i < MTILE * 16; i += NTHREADS) {
                int m = i >> 4, k = i & 15;
                const float* sp = &raw[m * 48 + k * 3];
                s[OFF_FEAT + k * 68 + m] =
                    sqrtf(sp[0]*sp[0] + sp[1]*sp[1] + sp[2]*sp[2]);
            }
        } else {
            for (int i = tid; i < MTILE * 8; i += NTHREADS) {
                int m = i >> 3, cc = i & 7;
                const float* sp = &raw[m * 72 + cc * 9];
                float q0 = sp[0], q1 = sp[1], q2 = sp[2];
                float q3 = sp[3], q4 = sp[4], q5 = sp[5];
                float q6 = sp[6], q7 = sp[7], q8 = sp[8];
                float tr = q0 + q4 + q8;
                float fb = sqrtf(q0*q0 + q1*q1 + q2*q2 + q3*q3 + q4*q4 +
                                 q5*q5 + q6*q6 + q7*q7 + q8*q8);
                s[OFF_FEAT + (2 * cc)     * 68 + m] = tr;
                s[OFF_FEAT + (2 * cc + 1) * 68 + m] = fb;
            }
        }
        __syncthreads();               // feat(c) ready

        // ---- GEMM1 FMA over 16 k-rows ----
        const float* wb = &s[OFF_W1B + (c & 1) * 2560];
#pragma unroll 4
        for (int k = 0; k < 16; ++k) {
            const float4 a4 = *reinterpret_cast<const float4*>(
                &s[OFF_FEAT + k * 68 + tm]);
            ull avd[4];
            avd[0] = pk2(a4.x, a4.x);
            avd[1] = pk2(a4.y, a4.y);
            avd[2] = pk2(a4.z, a4.z);
            avd[3] = pk2(a4.w, a4.w);
            const ull* bp = reinterpret_cast<const ull*>(&wb[k * 160 + tn]);
            ull bv2[5];
#pragma unroll
            for (int j = 0; j < 5; ++j) bv2[j] = bp[j];
#pragma unroll
            for (int i = 0; i < 4; ++i)
#pragma unroll
                for (int j = 0; j < 5; ++j)
                    fma2(accp[i][j], avd[i], bv2[j]);
        }
    }
    __syncthreads();   // buffers dead; hT overlays

    // ---------------- bias + SiLU -> hT [160][68] ---------------------------
#pragma unroll
    for (int j2 = 0; j2 < 5; ++j2) {
        const float b_lo = b1[tn + 2 * j2];
        const float b_hi = b1[tn + 2 * j2 + 1];
#pragma unroll
        for (int i = 0; i < 4; ++i) {
            float lo, hi;
            upk2(lo, hi, accp[i][j2]);
            float x0 = lo + b_lo, x1 = hi + b_hi;
            s[OFF_HT + (tn + 2 * j2)     * 68 + tm + i] = x0 / (1.0f + __expf(-x0));
            s[OFF_HT + (tn + 2 * j2 + 1) * 68 + tm + i] = x1 / (1.0f + __expf(-x1));
        }
    }
    __syncthreads();

    // ---------------- GEMM2: [64,160] @ [160,64] ----------------------------
    const int tn2 = (tid >> 4) * 4;
    ull acc2p[4][2];
#pragma unroll
    for (int i = 0; i < 4; ++i) { acc2p[i][0] = 0ULL; acc2p[i][1] = 0ULL; }

#pragma unroll 4
    for (int k = 0; k < 160; ++k) {
        const float4 a4 = *reinterpret_cast<const float4*>(&s[OFF_HT + k * 68 + tm]);
        const ulonglong2 b2v = *reinterpret_cast<const ulonglong2*>(
            &W2[(size_t)k * 64 + tn2]);
        ull avd[4];
        avd[0] = pk2(a4.x, a4.x);
        avd[1] = pk2(a4.y, a4.y);
        avd[2] = pk2(a4.z, a4.z);
        avd[3] = pk2(a4.w, a4.w);
#pragma unroll
        for (int i = 0; i < 4; ++i) {
            fma2(acc2p[i][0], avd[i], b2v.x);
            fma2(acc2p[i][1], avd[i], b2v.y);
        }
    }
    __syncthreads();   // hT dead; alpha + epilogue stage overlay

    // ---- issue first two epilogue t-chunks ASAP (overlap with alpha store) -
#define EPI_ISSUE(c)                                                          \
    do {                                                                      \
        const uint32_t edst = sbase + (OFF_EST + ((c) & 1) * 4864) * 4;       \
        for (int i = tid; i < 1152; i += NTHREADS) {                          \
            int nd = i / 18, q = i - nd * 18;                                 \
            if (nd < mlim)                                                    \
                cpa16(edst + (nd * EPITCH + q * 4) * 4,                       \
                      t + (size_t)(m0 + nd) * 576 + (c) * 72 + q * 4);        \
        }                                                                     \
        asm volatile("cp.async.commit_group;");                               \
    } while (0)

    EPI_ISSUE(0);
    EPI_ISSUE(1);

    // alphas + batch -> smem
    {
        const float b_0 = b2[tn2 + 0], b_1 = b2[tn2 + 1];
        const float b_2 = b2[tn2 + 2], b_3 = b2[tn2 + 3];
#pragma unroll
        for (int i = 0; i < 4; ++i) {
            float a0, a1, a2, a3;
            upk2(a0, a1, acc2p[i][0]);
            upk2(a2, a3, acc2p[i][1]);
            float* ap = &s[OFF_ALPHA + (tm + i) * 65 + tn2];
            ap[0] = a0 + b_0;
            ap[1] = a1 + b_1;
            ap[2] = a2 + b_2;
            ap[3] = a3 + b_3;
        }
    }
    if (tid < MTILE)
        reinterpret_cast<int*>(s)[OFF_BATCH + tid] =
            (tid < mlim) ? batch[m0 + tid] : -1;
    __syncthreads();

    // ------------- epilogue: pipelined gated sum over 8 t-chunks ------------
    const int node = tid >> 2;         // 0..63
    const int jj   = tid & 3;          // channels (8c + jj) and (8c + jj + 4)
    float g[9];
#pragma unroll
    for (int k = 0; k < 9; ++k) g[k] = 0.0f;

    for (int c = 0; c < 8; ++c) {
        if (c == 7) asm volatile("cp.async.wait_group 0;");
        else        asm volatile("cp.async.wait_group 1;");
        __syncthreads();               // chunk c visible to all threads
        if (node < mlim) {
            const float* ap = &s[OFF_ALPHA + node * 65 + c * 8];
            const float* fbase = &s[OFF_EST + (c & 1) * 4864 + node * EPITCH];
#pragma unroll
            for (int cc = 0; cc < 2; ++cc) {
                const int ch = jj + 4 * cc;
                const float al = ap[ch];
                const float* f = fbase + ch * 9;
#pragma unroll
                for (int k = 0; k < 9; ++k)
                    g[k] = fmaf(al, f[k], g[k]);
            }
        }
        __syncthreads();               // buffer (c&1) consumed
        if (c + 2 < 8) EPI_ISSUE(c + 2);
    }

    // reduce across the 4 lanes of this node
#pragma unroll
    for (int k = 0; k < 9; ++k) {
        g[k] += __shfl_xor_sync(0xFFFFFFFFu, g[k], 1);
        g[k] += __shfl_xor_sync(0xFFFFFFFFu, g[k], 2);
    }

    if (jj == 0) {
        float G[9];
        if (node < mlim) {
            float S[9];
#pragma unroll
            for (int a = 0; a < 3; ++a)
#pragma unroll
                for (int b = 0; b < 3; ++b)
                    S[a * 3 + b] = 0.5f * (g[a * 3 + b] + g[b * 3 + a]);
            const float* rp = frames + (size_t)(m0 + node) * 9;
            float R[9];
#pragma unroll
            for (int k = 0; k < 9; ++k) R[k] = rp[k];
            float P[9];
#pragma unroll
            for (int a = 0; a < 3; ++a)
#pragma unroll
                for (int c2 = 0; c2 < 3; ++c2)
                    P[a * 3 + c2] = R[a * 3 + 0] * S[0 * 3 + c2]
                                  + R[a * 3 + 1] * S[1 * 3 + c2]
                                  + R[a * 3 + 2] * S[2 * 3 + c2];
#pragma unroll
            for (int a = 0; a < 3; ++a)
#pragma unroll
                for (int d = 0; d < 3; ++d)
                    G[a * 3 + d] = P[a * 3 + 0] * R[d * 3 + 0]
                                 + P[a * 3 + 1] * R[d * 3 + 1]
                                 + P[a * 3 + 2] * R[d * 3 + 2];
        } else {
#pragma unroll
            for (int k = 0; k < 9; ++k) G[k] = 0.0f;
        }
#pragma unroll
        for (int k = 0; k < 9; ++k) s[OFF_GS + node * 9 + k] = G[k];
    }
    __syncthreads();

    // ---------------- sorted-run segment sum --------------------------------
    if (tid < 9) {
        const int* bs = reinterpret_cast<const int*>(s) + OFF_BATCH;
        int cur = bs[0];
        float run = 0.0f;
        for (int n = 0; n < mlim; ++n) {
            int b = bs[n];
            if (b != cur) {
                if ((unsigned)cur < (unsigned)num_graphs)
                    atomicAdd(&out[(size_t)cur * 9 + tid], run);
                run = 0.0f;
                cur = b;
            }
            run += s[OFF_GS + n * 9 + tid];
        }
        if ((unsigned)cur < (unsigned)num_graphs)
            atomicAdd(&out[(size_t)cur * 9 + tid], run);
    }
}

// ================================ launcher ==================================
extern "C" void kernel_launch(void* const* d_in, const int* in_sizes, int n_in,
                              void* d_out, int out_size)
{
    const float* h      = (const float*)d_in[0];
    const float* v      = (const float*)d_in[1];
    const float* t      = (const float*)d_in[2];
    const float* frames = (const float*)d_in[3];
    const int*   batch  = (const int*)d_in[4];
    const float* W1     = (const float*)d_in[5];
    const float* b1     = (const float*)d_in[6];
    const float* W2     = (const float*)d_in[7];
    const float* b2     = (const float*)d_in[8];
    float* out = (float*)d_out;

    const int N = in_sizes[0] / 128;
    const int num_graphs = out_size / 9;
    const int grid = (N + MTILE - 1) / MTILE;

    cudaMemsetAsync(d_out, 0, (size_t)out_size * sizeof(float));

    cudaFuncSetAttribute(tensor_message_fused,
                         cudaFuncAttributeMaxDynamicSharedMemorySize, SMEM_BYTES);

    tensor_message_fused<<<grid, NTHREADS, SMEM_BYTES>>>(
        h, v, t, frames, batch, W1, b1, W2, b2, out, N, num_graphs);
}